// round 1
// baseline (speedup 1.0000x reference)
#include <cuda_runtime.h>

#define B_ 256
#define C_ 6
#define T_ 2048
#define H_ 16
#define NDIR (B_*C_*2)   // 3072 warps per layer

// Layer-0 output sequence: y[b][c][t][0:16]=fwd h, [16:32]=bwd h  (fp32, ~403MB)
__device__ float g_y[(size_t)B_ * C_ * T_ * 32 + 32];

__device__ __forceinline__ float ex2f(float x){ float y; asm("ex2.approx.f32 %0, %1;" : "=f"(y) : "f"(x)); return y; }
__device__ __forceinline__ float rcpf(float x){ float y; asm("rcp.approx.f32 %0, %1;" : "=f"(y) : "f"(x)); return y; }

// sigmoid(x) = 1/(1+2^(-x*log2e))   -- saturation safe (inf -> 0/1, no NaN)
__device__ __forceinline__ float sigm(float x){
    return rcpf(1.0f + ex2f(-1.4426950408889634f * x));
}
// tanh(x) = 1 - 2/(1+2^(2x*log2e)) -- saturation safe
__device__ __forceinline__ float tanhfast(float x){
    return 1.0f - 2.0f * rcpf(1.0f + ex2f(2.8853900817779268f * x));
}

// ---------------------------------------------------------------------------
// Layer 0: input size 1, H=16, bidirectional. One warp per (b, c, dir).
// Lane L owns gates L and L+32 of the 64 gate pre-activations.
// Gate layout: [0:16)=i, [16:32)=f, [32:48)=g, [48:64)=o
//   acc0 (gate L):    L<16 -> i_L (sigmoid),  L>=16 -> f_{L-16} (sigmoid)
//   acc1 (gate L+32): L<16 -> g_L (tanh),     L>=16 -> o_{L-16} (sigmoid)
// State h_j, c_j live in lane j (j<16).
// ---------------------------------------------------------------------------
__global__ __launch_bounds__(256) void lstm_l0(
    const float* __restrict__ data,   // [B, C, T, 1]
    const float* __restrict__ Wih,    // [C, 2, 64, 1]
    const float* __restrict__ Whh,    // [C, 2, 64, 16]
    const float* __restrict__ bih,    // [C, 2, 64]
    const float* __restrict__ bhh)    // [C, 2, 64]
{
    const int gw   = (blockIdx.x * 256 + threadIdx.x) >> 5;
    const int lane = threadIdx.x & 31;
    if (gw >= NDIR) return;
    const int d  = gw & 1;
    const int bc = gw >> 1;
    const int c  = bc % C_;
    const int b  = bc / C_;
    const int cd = c * 2 + d;

    // per-thread weights (rows lane and lane+32)
    const float wi0   = Wih[cd*64 + lane];
    const float wi1   = Wih[cd*64 + 32 + lane];
    const float bias0 = bih[cd*64 + lane]      + bhh[cd*64 + lane];
    const float bias1 = bih[cd*64 + 32 + lane] + bhh[cd*64 + 32 + lane];
    float wh0[H_], wh1[H_];
    #pragma unroll
    for (int k = 0; k < H_; k++){
        wh0[k] = Whh[(cd*64 + lane)*H_ + k];
        wh1[k] = Whh[(cd*64 + 32 + lane)*H_ + k];
    }

    // branchless activation select for acc1: tanh (lane<16) vs sigmoid
    const bool  lo = (lane < H_);
    const float S1 = lo ?  2.8853900817779268f : -1.4426950408889634f;
    const float A1 = lo ?  1.0f : 0.0f;
    const float B1 = lo ? -2.0f : 1.0f;

    const float* xcur = data + (size_t)(b*C_ + c)*T_ + (d ? (T_-1) : 0);
    const int    dt   = d ? -1 : 1;
    float* ycur = g_y + ((size_t)(b*C_ + c)*T_ + (d ? (T_-1) : 0)) * 32 + d*16 + lane;
    const long   ystep = (long)dt * 32;

    float h = 0.0f, cst = 0.0f;
    for (int s = 0; s < T_; s++){
        const float x = __ldg(xcur);
        xcur += dt;
        float acc0 = fmaf(x, wi0, bias0);
        float acc1 = fmaf(x, wi1, bias1);
        #pragma unroll
        for (int k = 0; k < H_; k++){
            const float hk = __shfl_sync(0xffffffffu, h, k);
            acc0 = fmaf(wh0[k], hk, acc0);
            acc1 = fmaf(wh1[k], hk, acc1);
        }
        const float a0 = sigm(acc0);                                   // i or f
        const float a1 = fmaf(B1, rcpf(1.0f + ex2f(S1 * acc1)), A1);   // g or o
        const float fo0 = __shfl_xor_sync(0xffffffffu, a0, 16);        // f_j (lanes<16)
        const float fo1 = __shfl_xor_sync(0xffffffffu, a1, 16);        // o_j (lanes<16)
        cst = fmaf(fo0, cst, a0 * a1);      // c = f*c + i*g   (valid lanes<16)
        h   = fo1 * tanhfast(cst);          // h = o*tanh(c)
        if (lo) *ycur = h;
        ycur += ystep;
    }
}

// ---------------------------------------------------------------------------
// Layer 1: input size 32 (concat fwd/bwd of layer 0), H=16, bidirectional.
// One warp per (b, c, dir). Same gate ownership as layer 0.
// Only final h is written to out[b][c*32 + d*16 + j].
// ---------------------------------------------------------------------------
__global__ __launch_bounds__(256) void lstm_l1(
    const float* __restrict__ Wih,    // [C, 2, 64, 32]
    const float* __restrict__ Whh,    // [C, 2, 64, 16]
    const float* __restrict__ bih,    // [C, 2, 64]
    const float* __restrict__ bhh,    // [C, 2, 64]
    float* __restrict__ out)          // [B, C*32]
{
    const int gw   = (blockIdx.x * 256 + threadIdx.x) >> 5;
    const int lane = threadIdx.x & 31;
    if (gw >= NDIR) return;
    const int d  = gw & 1;
    const int bc = gw >> 1;
    const int c  = bc % C_;
    const int b  = bc / C_;
    const int cd = c * 2 + d;

    float wi0[32], wi1[32];
    #pragma unroll
    for (int k = 0; k < 32; k++){
        wi0[k] = Wih[(cd*64 + lane)*32 + k];
        wi1[k] = Wih[(cd*64 + 32 + lane)*32 + k];
    }
    float wh0[H_], wh1[H_];
    #pragma unroll
    for (int k = 0; k < H_; k++){
        wh0[k] = Whh[(cd*64 + lane)*H_ + k];
        wh1[k] = Whh[(cd*64 + 32 + lane)*H_ + k];
    }
    const float bias0 = bih[cd*64 + lane]      + bhh[cd*64 + lane];
    const float bias1 = bih[cd*64 + 32 + lane] + bhh[cd*64 + 32 + lane];

    const bool  lo = (lane < H_);
    const float S1 = lo ?  2.8853900817779268f : -1.4426950408889634f;
    const float A1 = lo ?  1.0f : 0.0f;
    const float B1 = lo ? -2.0f : 1.0f;

    const float4* yc = (const float4*)(g_y + (size_t)(b*C_ + c)*T_*32) + (d ? (T_-1) : 0) * 8;
    const long    ys = (d ? -8l : 8l);

    float h = 0.0f, cst = 0.0f;
    for (int s = 0; s < T_; s++){
        // load this step's 32-float input (same address across lanes -> L1 broadcast)
        float ya[32];
        #pragma unroll
        for (int q = 0; q < 8; q++){
            const float4 v = __ldg(yc + q);
            ya[4*q+0] = v.x; ya[4*q+1] = v.y; ya[4*q+2] = v.z; ya[4*q+3] = v.w;
        }
        yc += ys;

        float acc0 = bias0;
        float acc1 = bias1;
        // recurrent part first (independent of y loads -> covers load latency)
        #pragma unroll
        for (int k = 0; k < H_; k++){
            const float hk = __shfl_sync(0xffffffffu, h, k);
            acc0 = fmaf(wh0[k], hk, acc0);
            acc1 = fmaf(wh1[k], hk, acc1);
        }
        #pragma unroll
        for (int k = 0; k < 32; k++){
            acc0 = fmaf(wi0[k], ya[k], acc0);
            acc1 = fmaf(wi1[k], ya[k], acc1);
        }

        const float a0 = sigm(acc0);
        const float a1 = fmaf(B1, rcpf(1.0f + ex2f(S1 * acc1)), A1);
        const float fo0 = __shfl_xor_sync(0xffffffffu, a0, 16);
        const float fo1 = __shfl_xor_sync(0xffffffffu, a1, 16);
        cst = fmaf(fo0, cst, a0 * a1);
        h   = fo1 * tanhfast(cst);
    }

    if (lo) out[b*(C_*32) + c*32 + d*16 + lane] = h;
}

extern "C" void kernel_launch(void* const* d_in, const int* in_sizes, int n_in,
                              void* d_out, int out_size)
{
    const float* data = (const float*)d_in[0];
    const float* Wih0 = (const float*)d_in[1];
    const float* Whh0 = (const float*)d_in[2];
    const float* bih0 = (const float*)d_in[3];
    const float* bhh0 = (const float*)d_in[4];
    const float* Wih1 = (const float*)d_in[5];
    const float* Whh1 = (const float*)d_in[6];
    const float* bih1 = (const float*)d_in[7];
    const float* bhh1 = (const float*)d_in[8];

    const int blocks = (NDIR * 32) / 256;   // 384 blocks x 256 threads = 3072 warps
    lstm_l0<<<blocks, 256>>>(data, Wih0, Whh0, bih0, bhh0);
    lstm_l1<<<blocks, 256>>>(Wih1, Whh1, bih1, bhh1, (float*)d_out);
}

// round 3
// speedup vs baseline: 1.0872x; 1.0872x over previous
#include <cuda_runtime.h>

#define B_ 256
#define C_ 6
#define T_ 2048
#define H_ 16
#define NDIR (B_*C_*2)   // 3072 warps per recurrent layer
#define PAD 128

// Layer-0 output sequence: y[b][c][t][0:16]=fwd h, [16:32]=bwd h  (fp32, ~403MB)
__device__ float g_y[(size_t)B_ * C_ * T_ * 32];
// Layer-1 input pre-activations: pre[cd][b][t][64]  (fp32, ~1.61GB) + pad both ends
__device__ float g_pre[(size_t)12 * B_ * T_ * 64 + 2 * PAD];

__device__ __forceinline__ float ex2f(float x){ float y; asm("ex2.approx.f32 %0, %1;" : "=f"(y) : "f"(x)); return y; }
__device__ __forceinline__ float rcpf(float x){ float y; asm("rcp.approx.f32 %0, %1;" : "=f"(y) : "f"(x)); return y; }

// sigmoid(x) = 1/(1+2^(-x*log2e))   -- saturation safe
__device__ __forceinline__ float sigm(float x){
    return rcpf(1.0f + ex2f(-1.4426950408889634f * x));
}
// tanh(x) = 1 - 2/(1+2^(2x*log2e)) -- saturation safe
__device__ __forceinline__ float tanhfast(float x){
    return 1.0f - 2.0f * rcpf(1.0f + ex2f(2.8853900817779268f * x));
}

// ---- packed f32x2 helpers ----
typedef unsigned long long u64t;
__device__ __forceinline__ u64t pk(float a, float b){
    u64t r; asm("mov.b64 %0, {%1,%2};" : "=l"(r) : "f"(a), "f"(b)); return r;
}
__device__ __forceinline__ void upk(u64t v, float& a, float& b){
    asm("mov.b64 {%0,%1}, %2;" : "=f"(a), "=f"(b) : "l"(v));
}
__device__ __forceinline__ u64t ffma2(u64t a, u64t b, u64t c){
    u64t d; asm("fma.rn.f32x2 %0, %1, %2, %3;" : "=l"(d) : "l"(a), "l"(b), "l"(c)); return d;
}

// ---------------------------------------------------------------------------
// Layer 0: input size 1, H=16, bidirectional. One warp per (b, c, dir).
// Lane L owns gates L and L+32. Gate layout: [i(16) f(16) g(16) o(16)].
//   acc0 (gate L):    L<16 -> i_L,  L>=16 -> f_{L-16}   (both sigmoid)
//   acc1 (gate L+32): L<16 -> g_L (tanh), L>=16 -> o_{L-16} (sigmoid)
// State h_j, c_j live in lane j (j<16); h broadcast via ping-pong smem.
// ---------------------------------------------------------------------------
__global__ __launch_bounds__(256, 3) void lstm_l0(
    const float* __restrict__ data,   // [B, C, T, 1]
    const float* __restrict__ Wih,    // [C, 2, 64, 1]
    const float* __restrict__ Whh,    // [C, 2, 64, 16]
    const float* __restrict__ bih,    // [C, 2, 64]
    const float* __restrict__ bhh)    // [C, 2, 64]
{
    __shared__ __align__(16) float hsm[2][8][16];
    const int warp = threadIdx.x >> 5;
    const int lane = threadIdx.x & 31;
    const int gw   = blockIdx.x * 8 + warp;     // exactly NDIR warps in grid
    const int d  = gw & 1;
    const int bc = gw >> 1;
    const int c  = bc % C_;
    const int b  = bc / C_;
    const int cd = c * 2 + d;

    const float wi0   = Wih[cd*64 + lane];
    const float wi1   = Wih[cd*64 + 32 + lane];
    const float bias0 = bih[cd*64 + lane]      + bhh[cd*64 + lane];
    const float bias1 = bih[cd*64 + 32 + lane] + bhh[cd*64 + 32 + lane];

    u64t whp0[8], whp1[8];
    #pragma unroll
    for (int j = 0; j < 8; j++){
        const float* r0 = Whh + (cd*64 + lane)*H_;
        const float* r1 = Whh + (cd*64 + 32 + lane)*H_;
        whp0[j] = pk(r0[2*j], r0[2*j+1]);
        whp1[j] = pk(r1[2*j], r1[2*j+1]);
    }

    const bool  lo = (lane < H_);
    const float S1 = lo ?  2.8853900817779268f : -1.4426950408889634f;
    const float A1 = lo ?  1.0f : 0.0f;
    const float B1 = lo ? -2.0f : 1.0f;

    const float* xcur = data + (size_t)(b*C_ + c)*T_ + (d ? (T_-1) : 0);
    const int    dt   = d ? -1 : 1;
    float* ycur = g_y + ((size_t)(b*C_ + c)*T_ + (d ? (T_-1) : 0)) * 32 + d*16 + lane;
    const long   ystep = (long)dt * 32;

    if (lo) hsm[0][warp][lane] = 0.0f;
    __syncwarp();

    float h = 0.0f, cst = 0.0f;
    int pb = 0;
    for (int s = 0; s < T_; s++){
        const float x = __ldg(xcur);   // broadcast, latency hidden under matvec
        xcur += dt;

        // read previous h as packed pairs (uniform address -> LDS broadcast)
        const ulonglong2* hv = (const ulonglong2*)hsm[pb][warp];
        const ulonglong2 v0 = hv[0], v1 = hv[1], v2 = hv[2], v3 = hv[3];
        const u64t hp[8] = { v0.x, v0.y, v1.x, v1.y, v2.x, v2.y, v3.x, v3.y };

        u64t a0A = pk(bias0, 0.0f), a0B = pk(0.0f, 0.0f);
        u64t a1A = pk(bias1, 0.0f), a1B = pk(0.0f, 0.0f);
        #pragma unroll
        for (int j = 0; j < 4; j++){
            a0A = ffma2(whp0[j],   hp[j],   a0A);
            a0B = ffma2(whp0[j+4], hp[j+4], a0B);
            a1A = ffma2(whp1[j],   hp[j],   a1A);
            a1B = ffma2(whp1[j+4], hp[j+4], a1B);
        }
        float x0,x1,x2,x3;
        upk(a0A, x0, x1); upk(a0B, x2, x3);
        const float acc0 = fmaf(x, wi0, (x0 + x1) + (x2 + x3));
        upk(a1A, x0, x1); upk(a1B, x2, x3);
        const float acc1 = fmaf(x, wi1, (x0 + x1) + (x2 + x3));

        const float a0 = sigm(acc0);                                   // i or f
        const float a1 = fmaf(B1, rcpf(1.0f + ex2f(S1 * acc1)), A1);   // g or o
        const float fo0 = __shfl_xor_sync(0xffffffffu, a0, 16);        // f_j (lanes<16)
        const float fo1 = __shfl_xor_sync(0xffffffffu, a1, 16);        // o_j (lanes<16)
        cst = fmaf(fo0, cst, a0 * a1);
        h   = fo1 * tanhfast(cst);

        if (lo){ hsm[pb ^ 1][warp][lane] = h; *ycur = h; }
        __syncwarp();
        pb ^= 1;
        ycur += ystep;
    }
}

// ---------------------------------------------------------------------------
// Layer-1 input GEMM: pre[cd][b][t][g] = sum_k Wih1[cd][g][k]*y[b][c][t][k] + bias[g]
// Block per (cd, b): 8 warps x 256 t-rows each. Lane owns gates (lane, lane+32).
// Pure throughput kernel: packed f32x2 FMAs, broadcast y loads, coalesced stores.
// ---------------------------------------------------------------------------
__global__ __launch_bounds__(256) void l1_pre(
    const float* __restrict__ Wih,    // [C, 2, 64, 32]
    const float* __restrict__ bih,
    const float* __restrict__ bhh)
{
    const int blk  = blockIdx.x;      // 0..3071
    const int cd   = blk >> 8;
    const int b    = blk & 255;
    const int c    = cd >> 1;
    const int warp = threadIdx.x >> 5;
    const int lane = threadIdx.x & 31;

    u64t w0[16], w1[16];
    {
        const float* r0 = Wih + (size_t)(cd*64 + lane)*32;
        const float* r1 = Wih + (size_t)(cd*64 + 32 + lane)*32;
        #pragma unroll
        for (int j = 0; j < 16; j++){
            w0[j] = pk(r0[2*j], r0[2*j+1]);
            w1[j] = pk(r1[2*j], r1[2*j+1]);
        }
    }
    const float bias0 = bih[cd*64 + lane]      + bhh[cd*64 + lane];
    const float bias1 = bih[cd*64 + 32 + lane] + bhh[cd*64 + 32 + lane];

    const float* ybase = g_y + ((size_t)(b*C_ + c)*T_)*32;
    float*       pbase = g_pre + PAD + ((size_t)(cd*B_ + b)*T_)*64;

    const int t0 = warp * 256;
    #pragma unroll 2
    for (int t = t0; t < t0 + 256; t++){
        const ulonglong2* yr = (const ulonglong2*)(ybase + (size_t)t*32);
        u64t y[16];
        #pragma unroll
        for (int q = 0; q < 8; q++){
            const ulonglong2 v = yr[q];   // broadcast across warp
            y[2*q]   = v.x;
            y[2*q+1] = v.y;
        }
        u64t a0A = pk(bias0, 0.0f), a0B = pk(0.0f, 0.0f);
        u64t a1A = pk(bias1, 0.0f), a1B = pk(0.0f, 0.0f);
        #pragma unroll
        for (int j = 0; j < 8; j++){
            a0A = ffma2(w0[j],   y[j],   a0A);
            a0B = ffma2(w0[j+8], y[j+8], a0B);
            a1A = ffma2(w1[j],   y[j],   a1A);
            a1B = ffma2(w1[j+8], y[j+8], a1B);
        }
        float x0,x1,x2,x3;
        upk(a0A, x0, x1); upk(a0B, x2, x3);
        const float p0 = (x0 + x1) + (x2 + x3);
        upk(a1A, x0, x1); upk(a1B, x2, x3);
        const float p1 = (x0 + x1) + (x2 + x3);

        float* pr = pbase + (size_t)t*64;
        pr[lane]      = p0;   // coalesced 128B
        pr[lane + 32] = p1;
    }
}

// ---------------------------------------------------------------------------
// Layer 1 recurrence: input pre-activations precomputed; per step only the
// h-matvec (64x16) + activations. One warp per (b, c, dir). Distance-2
// prefetch of pre (DRAM-latency loads). Single wave at 24 warps/SM.
// ---------------------------------------------------------------------------
__global__ __launch_bounds__(256, 3) void lstm_l1(
    const float* __restrict__ Whh,    // [C, 2, 64, 16]
    float* __restrict__ out)          // [B, C*32]
{
    __shared__ __align__(16) float hsm[2][8][16];
    const int warp = threadIdx.x >> 5;
    const int lane = threadIdx.x & 31;
    const int gw   = blockIdx.x * 8 + warp;
    const int d  = gw & 1;
    const int bc = gw >> 1;
    const int c  = bc % C_;
    const int b  = bc / C_;
    const int cd = c * 2 + d;

    u64t whp0[8], whp1[8];
    #pragma unroll
    for (int j = 0; j < 8; j++){
        const float* r0 = Whh + (cd*64 + lane)*H_;
        const float* r1 = Whh + (cd*64 + 32 + lane)*H_;
        whp0[j] = pk(r0[2*j], r0[2*j+1]);
        whp1[j] = pk(r1[2*j], r1[2*j+1]);
    }

    const bool  lo = (lane < H_);
    const float S1 = lo ?  2.8853900817779268f : -1.4426950408889634f;
    const float A1 = lo ?  1.0f : 0.0f;
    const float B1 = lo ? -2.0f : 1.0f;

    const float* pp = g_pre + PAD
        + (((size_t)(cd*B_ + b))*T_ + (d ? (T_-1) : 0))*64 + lane;
    const long pstep = d ? -64l : 64l;

    // distance-2 prefetch pipeline (padding makes over/underrun safe)
    float p0  = __ldg(pp), p1  = __ldg(pp + 32);  pp += pstep;
    float q0  = __ldg(pp), q1  = __ldg(pp + 32);  pp += pstep;

    if (lo) hsm[0][warp][lane] = 0.0f;
    __syncwarp();

    float h = 0.0f, cst = 0.0f;
    int pb = 0;
    for (int s = 0; s < T_; s++){
        const float r0 = __ldg(pp), r1 = __ldg(pp + 32);   // for s+2
        pp += pstep;

        const ulonglong2* hv = (const ulonglong2*)hsm[pb][warp];
        const ulonglong2 v0 = hv[0], v1 = hv[1], v2 = hv[2], v3 = hv[3];
        const u64t hp[8] = { v0.x, v0.y, v1.x, v1.y, v2.x, v2.y, v3.x, v3.y };

        u64t a0A = pk(p0, 0.0f), a0B = pk(0.0f, 0.0f);
        u64t a1A = pk(p1, 0.0f), a1B = pk(0.0f, 0.0f);
        #pragma unroll
        for (int j = 0; j < 4; j++){
            a0A = ffma2(whp0[j],   hp[j],   a0A);
            a0B = ffma2(whp0[j+4], hp[j+4], a0B);
            a1A = ffma2(whp1[j],   hp[j],   a1A);
            a1B = ffma2(whp1[j+4], hp[j+4], a1B);
        }
        float x0,x1,x2,x3;
        upk(a0A, x0, x1); upk(a0B, x2, x3);
        const float acc0 = (x0 + x1) + (x2 + x3);
        upk(a1A, x0, x1); upk(a1B, x2, x3);
        const float acc1 = (x0 + x1) + (x2 + x3);

        const float a0 = sigm(acc0);
        const float a1 = fmaf(B1, rcpf(1.0f + ex2f(S1 * acc1)), A1);
        const float fo0 = __shfl_xor_sync(0xffffffffu, a0, 16);
        const float fo1 = __shfl_xor_sync(0xffffffffu, a1, 16);
        cst = fmaf(fo0, cst, a0 * a1);
        h   = fo1 * tanhfast(cst);

        if (lo) hsm[pb ^ 1][warp][lane] = h;
        __syncwarp();
        pb ^= 1;
        p0 = q0; p1 = q1;
        q0 = r0; q1 = r1;
    }

    if (lo) out[b*(C_*32) + c*32 + d*16 + lane] = h;
}

extern "C" void kernel_launch(void* const* d_in, const int* in_sizes, int n_in,
                              void* d_out, int out_size)
{
    const float* data = (const float*)d_in[0];
    const float* Wih0 = (const float*)d_in[1];
    const float* Whh0 = (const float*)d_in[2];
    const float* bih0 = (const float*)d_in[3];
    const float* bhh0 = (const float*)d_in[4];
    const float* Wih1 = (const float*)d_in[5];
    const float* Whh1 = (const float*)d_in[6];
    const float* bih1 = (const float*)d_in[7];
    const float* bhh1 = (const float*)d_in[8];

    const int blocks = NDIR / 8;   // 384 blocks x 8 warps = 3072 warps
    lstm_l0<<<blocks, 256>>>(data, Wih0, Whh0, bih0, bhh0);
    l1_pre<<<12 * B_, 256>>>(Wih1, bih1, bhh1);
    lstm_l1<<<blocks, 256>>>(Whh1, (float*)d_out);
}

// round 4
// speedup vs baseline: 1.1083x; 1.0194x over previous
#include <cuda_runtime.h>

#define B_ 256
#define C_ 6
#define T_ 2048
#define H_ 16
#define NDIR (B_*C_*2)   // 3072 warps per recurrent layer
#define PADF 512         // floats of padding on each side of g_pre (prefetch overrun)

#define L2E  1.4426950408889634f
#define L2E2 2.8853900817779268f

// Layer-0 output sequence: y[b][c][t][0:16]=fwd h, [16:32]=bwd h  (fp32, ~403MB)
__device__ __align__(16) float g_y[(size_t)B_ * C_ * T_ * 32];
// Layer-1 pre-activations (prescaled by ex2 constants, bias included):
// pre[cd][b][t][64], interleaved per lane: [2*lane]=gate(lane), [2*lane+1]=gate(lane+32)
__device__ __align__(16) float g_pre[(size_t)12 * B_ * T_ * 64 + 2 * PADF];

__device__ __forceinline__ float ex2f(float x){ float y; asm("ex2.approx.f32 %0, %1;" : "=f"(y) : "f"(x)); return y; }
__device__ __forceinline__ float rcpf(float x){ float y; asm("rcp.approx.f32 %0, %1;" : "=f"(y) : "f"(x)); return y; }

// tanh(x) = 1 - 2/(1+2^(2x*log2e)) -- saturation safe, ~1e-6 abs err
__device__ __forceinline__ float tanhfast(float x){
    return 1.0f - 2.0f * rcpf(1.0f + ex2f(L2E2 * x));
}

// ---- packed f32x2 helpers ----
typedef unsigned long long u64t;
__device__ __forceinline__ u64t pk(float a, float b){
    u64t r; asm("mov.b64 %0, {%1,%2};" : "=l"(r) : "f"(a), "f"(b)); return r;
}
__device__ __forceinline__ void upk(u64t v, float& a, float& b){
    asm("mov.b64 {%0,%1}, %2;" : "=f"(a), "=f"(b) : "l"(v));
}
__device__ __forceinline__ u64t ffma2(u64t a, u64t b, u64t c){
    u64t d; asm("fma.rn.f32x2 %0, %1, %2, %3;" : "=l"(d) : "l"(a), "l"(b), "l"(c)); return d;
}
__device__ __forceinline__ u64t add2(u64t a, u64t b){
    u64t d; asm("add.rn.f32x2 %0, %1, %2;" : "=l"(d) : "l"(a), "l"(b)); return d;
}

// Gate prescale: row `lane` (i/f gates) -> -log2e (sigmoid), row `lane+32`:
// lane<16 -> g gate (tanh, +2log2e), lane>=16 -> o gate (sigmoid, -log2e).
// After prescale: sigmoid = rcp(1+ex2(acc)); tanh = 1-2*rcp(1+ex2(acc)).

// ---------------------------------------------------------------------------
// Layer 0: input size 1, H=16, bidirectional. One warp per (b, c, dir).
// Lane L owns gate rows L and L+32. State h_j, c_j valid in lanes j<16.
// h broadcast via ping-pong smem (STS + syncwarp + 4x LDS.128).
// ---------------------------------------------------------------------------
__global__ __launch_bounds__(256, 3) void lstm_l0(
    const float* __restrict__ data,   // [B, C, T, 1]
    const float* __restrict__ Wih,    // [C, 2, 64, 1]
    const float* __restrict__ Whh,    // [C, 2, 64, 16]
    const float* __restrict__ bih,    // [C, 2, 64]
    const float* __restrict__ bhh)    // [C, 2, 64]
{
    __shared__ __align__(16) float hsm[2][8][16];
    const int warp = threadIdx.x >> 5;
    const int lane = threadIdx.x & 31;
    const int gw   = blockIdx.x * 8 + warp;     // exactly NDIR warps in grid
    const int d  = gw & 1;
    const int bc = gw >> 1;
    const int c  = bc % C_;
    const int b  = bc / C_;
    const int cd = c * 2 + d;

    const bool  lo = (lane < H_);
    const float s0 = -L2E;
    const float s1 = lo ? L2E2 : -L2E;
    const float A1 = lo ?  1.0f : 0.0f;
    const float B1 = lo ? -2.0f : 1.0f;

    const float wi0   = s0 * Wih[cd*64 + lane];
    const float wi1   = s1 * Wih[cd*64 + 32 + lane];
    const float bias0 = s0 * (bih[cd*64 + lane]      + bhh[cd*64 + lane]);
    const float bias1 = s1 * (bih[cd*64 + 32 + lane] + bhh[cd*64 + 32 + lane]);

    u64t whp0[8], whp1[8];
    #pragma unroll
    for (int j = 0; j < 8; j++){
        const float* r0 = Whh + (cd*64 + lane)*H_;
        const float* r1 = Whh + (cd*64 + 32 + lane)*H_;
        whp0[j] = pk(s0*r0[2*j], s0*r0[2*j+1]);
        whp1[j] = pk(s1*r1[2*j], s1*r1[2*j+1]);
    }

    const float* xcur = data + (size_t)(b*C_ + c)*T_ + (d ? (T_-1) : 0);
    const int    dt   = d ? -1 : 1;
    float* ycur = g_y + ((size_t)(b*C_ + c)*T_ + (d ? (T_-1) : 0)) * 32 + d*16 + lane;
    const long   ystep = (long)dt * 32;

    if (lo) hsm[0][warp][lane] = 0.0f;
    __syncwarp();

    float h = 0.0f, cst = 0.0f;
    int pb = 0;
    for (int s = 0; s < T_; s++){
        const float x = __ldg(xcur);
        xcur += dt;

        const ulonglong2* hv = (const ulonglong2*)hsm[pb][warp];
        const ulonglong2 v0 = hv[0], v1 = hv[1], v2 = hv[2], v3 = hv[3];
        const u64t hp[8] = { v0.x, v0.y, v1.x, v1.y, v2.x, v2.y, v3.x, v3.y };

        u64t a0A = pk(bias0, 0.0f), a0B = pk(0.0f, 0.0f);
        u64t a1A = pk(bias1, 0.0f), a1B = pk(0.0f, 0.0f);
        #pragma unroll
        for (int j = 0; j < 4; j++){
            a0A = ffma2(whp0[j],   hp[j],   a0A);
            a0B = ffma2(whp0[j+4], hp[j+4], a0B);
            a1A = ffma2(whp1[j],   hp[j],   a1A);
            a1B = ffma2(whp1[j+4], hp[j+4], a1B);
        }
        float e0, e1, f0, f1;
        upk(add2(a0A, a0B), e0, e1);
        const float acc0 = fmaf(x, wi0, e0 + e1);
        upk(add2(a1A, a1B), f0, f1);
        const float acc1 = fmaf(x, wi1, f0 + f1);

        const float a0 = rcpf(1.0f + ex2f(acc0));                 // sigmoid (i or f)
        const float a1 = fmaf(B1, rcpf(1.0f + ex2f(acc1)), A1);   // tanh (g) or sigmoid (o)
        const float fo0 = __shfl_xor_sync(0xffffffffu, a0, 16);   // f_j (lanes<16)
        const float fo1 = __shfl_xor_sync(0xffffffffu, a1, 16);   // o_j (lanes<16)
        cst = fmaf(fo0, cst, a0 * a1);
        h   = fo1 * tanhfast(cst);

        if (lo){ hsm[pb ^ 1][warp][lane] = h; *ycur = h; }
        __syncwarp();
        pb ^= 1;
        ycur += ystep;
    }
}

// ---------------------------------------------------------------------------
// Layer-1 input GEMM: pre[cd][b][t][2g interleaved] = prescale * (Wih1.y_t + bias)
// Block per (cd, b): 8 warps x 256 t-rows. Lane owns gate rows (lane, lane+32).
// ---------------------------------------------------------------------------
__global__ __launch_bounds__(256) void l1_pre(
    const float* __restrict__ Wih,    // [C, 2, 64, 32]
    const float* __restrict__ bih,
    const float* __restrict__ bhh)
{
    const int blk  = blockIdx.x;      // 0..3071
    const int cd   = blk >> 8;
    const int b    = blk & 255;
    const int c    = cd >> 1;
    const int warp = threadIdx.x >> 5;
    const int lane = threadIdx.x & 31;

    const bool  lo = (lane < H_);
    const float s0 = -L2E;
    const float s1 = lo ? L2E2 : -L2E;

    u64t w0[16], w1[16];
    {
        const float* r0 = Wih + (size_t)(cd*64 + lane)*32;
        const float* r1 = Wih + (size_t)(cd*64 + 32 + lane)*32;
        #pragma unroll
        for (int j = 0; j < 16; j++){
            w0[j] = pk(s0*r0[2*j], s0*r0[2*j+1]);
            w1[j] = pk(s1*r1[2*j], s1*r1[2*j+1]);
        }
    }
    const float bias0 = s0 * (bih[cd*64 + lane]      + bhh[cd*64 + lane]);
    const float bias1 = s1 * (bih[cd*64 + 32 + lane] + bhh[cd*64 + 32 + lane]);

    const float* ybase = g_y + ((size_t)(b*C_ + c)*T_)*32;
    float*       pbase = g_pre + PADF + ((size_t)(cd*B_ + b)*T_)*64;

    const int t0 = warp * 256;
    #pragma unroll 2
    for (int t = t0; t < t0 + 256; t++){
        const ulonglong2* yr = (const ulonglong2*)(ybase + (size_t)t*32);
        u64t y[16];
        #pragma unroll
        for (int q = 0; q < 8; q++){
            const ulonglong2 v = yr[q];   // uniform address -> broadcast
            y[2*q]   = v.x;
            y[2*q+1] = v.y;
        }
        u64t a0A = pk(bias0, 0.0f), a0B = pk(0.0f, 0.0f);
        u64t a1A = pk(bias1, 0.0f), a1B = pk(0.0f, 0.0f);
        #pragma unroll
        for (int j = 0; j < 8; j++){
            a0A = ffma2(w0[j],   y[j],   a0A);
            a0B = ffma2(w0[j+8], y[j+8], a0B);
            a1A = ffma2(w1[j],   y[j],   a1A);
            a1B = ffma2(w1[j+8], y[j+8], a1B);
        }
        float e0, e1, f0, f1;
        upk(add2(a0A, a0B), e0, e1);
        upk(add2(a1A, a1B), f0, f1);

        // interleaved store: one STG.64 per thread, 256B coalesced per warp
        ((float2*)(pbase + (size_t)t*64))[lane] = make_float2(e0 + e1, f0 + f1);
    }
}

// ---------------------------------------------------------------------------
// Layer 1 recurrence: per step only the h-matvec (64x16) + activations.
// One warp per (b, c, dir); one LDG.64 per thread per step (interleaved pre),
// distance-4 prefetch (slack > DRAM latency). Single wave at 24 warps/SM.
// ---------------------------------------------------------------------------
__global__ __launch_bounds__(256, 3) void lstm_l1(
    const float* __restrict__ Whh,    // [C, 2, 64, 16]
    float* __restrict__ out)          // [B, C*32]
{
    __shared__ __align__(16) float hsm[2][8][16];
    const int warp = threadIdx.x >> 5;
    const int lane = threadIdx.x & 31;
    const int gw   = blockIdx.x * 8 + warp;
    const int d  = gw & 1;
    const int bc = gw >> 1;
    const int c  = bc % C_;
    const int b  = bc / C_;
    const int cd = c * 2 + d;

    const bool  lo = (lane < H_);
    const float s0 = -L2E;
    const float s1 = lo ? L2E2 : -L2E;
    const float A1 = lo ?  1.0f : 0.0f;
    const float B1 = lo ? -2.0f : 1.0f;

    u64t whp0[8], whp1[8];
    #pragma unroll
    for (int j = 0; j < 8; j++){
        const float* r0 = Whh + (cd*64 + lane)*H_;
        const float* r1 = Whh + (cd*64 + 32 + lane)*H_;
        whp0[j] = pk(s0*r0[2*j], s0*r0[2*j+1]);
        whp1[j] = pk(s1*r1[2*j], s1*r1[2*j+1]);
    }

    // pre pointer in float2 units: row stride = 32 float2
    const float2* pq = (const float2*)(g_pre + PADF)
        + (((size_t)(cd*B_ + b))*T_ + (d ? (T_-1) : 0))*32 + lane;
    const long pstep = d ? -32l : 32l;

    // distance-4 prefetch ring (PADF covers over/underrun; unused tail values
    // are loaded but never consumed)
    float2 rr[4];
    #pragma unroll
    for (int i = 0; i < 4; i++){ rr[i] = __ldg(pq); pq += pstep; }

    if (lo) hsm[0][warp][lane] = 0.0f;
    __syncwarp();

    float h = 0.0f, cst = 0.0f;
    int pb = 0;
    for (int s = 0; s < T_; s += 4){
        #pragma unroll
        for (int u = 0; u < 4; u++){
            const float2 nv = __ldg(pq);   // for step s+u+4
            pq += pstep;
            const float2 pv = rr[u];

            const ulonglong2* hv = (const ulonglong2*)hsm[pb][warp];
            const ulonglong2 v0 = hv[0], v1 = hv[1], v2 = hv[2], v3 = hv[3];
            const u64t hp[8] = { v0.x, v0.y, v1.x, v1.y, v2.x, v2.y, v3.x, v3.y };

            u64t a0A = pk(pv.x, 0.0f), a0B = pk(0.0f, 0.0f);
            u64t a1A = pk(pv.y, 0.0f), a1B = pk(0.0f, 0.0f);
            #pragma unroll
            for (int j = 0; j < 4; j++){
                a0A = ffma2(whp0[j],   hp[j],   a0A);
                a0B = ffma2(whp0[j+4], hp[j+4], a0B);
                a1A = ffma2(whp1[j],   hp[j],   a1A);
                a1B = ffma2(whp1[j+4], hp[j+4], a1B);
            }
            float e0, e1, f0, f1;
            upk(add2(a0A, a0B), e0, e1);
            const float acc0 = e0 + e1;
            upk(add2(a1A, a1B), f0, f1);
            const float acc1 = f0 + f1;

            const float a0 = rcpf(1.0f + ex2f(acc0));
            const float a1 = fmaf(B1, rcpf(1.0f + ex2f(acc1)), A1);
            const float fo0 = __shfl_xor_sync(0xffffffffu, a0, 16);
            const float fo1 = __shfl_xor_sync(0xffffffffu, a1, 16);
            cst = fmaf(fo0, cst, a0 * a1);
            h   = fo1 * tanhfast(cst);

            if (lo) hsm[pb ^ 1][warp][lane] = h;
            __syncwarp();
            pb ^= 1;
            rr[u] = nv;
        }
    }

    if (lo) out[b*(C_*32) + c*32 + d*16 + lane] = h;
}

extern "C" void kernel_launch(void* const* d_in, const int* in_sizes, int n_in,
                              void* d_out, int out_size)
{
    const float* data = (const float*)d_in[0];
    const float* Wih0 = (const float*)d_in[1];
    const float* Whh0 = (const float*)d_in[2];
    const float* bih0 = (const float*)d_in[3];
    const float* bhh0 = (const float*)d_in[4];
    const float* Wih1 = (const float*)d_in[5];
    const float* Whh1 = (const float*)d_in[6];
    const float* bih1 = (const float*)d_in[7];
    const float* bhh1 = (const float*)d_in[8];

    const int blocks = NDIR / 8;   // 384 blocks x 8 warps = 3072 warps
    lstm_l0<<<blocks, 256>>>(data, Wih0, Whh0, bih0, bhh0);
    l1_pre<<<12 * B_, 256>>>(Wih1, bih1, bhh1);
    lstm_l1<<<blocks, 256>>>(Whh1, (float*)d_out);
}

// round 7
// speedup vs baseline: 1.5154x; 1.3673x over previous
#include <cuda_runtime.h>

#define B_ 256
#define C_ 6
#define T_ 2048
#define H_ 16
#define NPAIR (B_/2*C_*2)   // 1536 warps: one per (batch-pair, channel, dir)
#define PADF 1024           // float padding each side of g_pre (prefetch overrun)

#define L2E  1.4426950408889634f
#define L2E2 2.8853900817779268f

// Layer-0 output sequence: y[b][c][t][0:16]=fwd h, [16:32]=bwd h  (fp32, ~403MB)
__device__ __align__(16) float g_y[(size_t)B_ * C_ * T_ * 32];
// Layer-1 pre-activations, batch-pair interleaved:
// pre[cd][q][t][g*2+par], q=b>>1, par=b&1, g in [0,64). Prescaled, bias included.
__device__ __align__(16) float g_pre[(size_t)12 * 128 * T_ * 128 + 2 * PADF];

__device__ __forceinline__ float ex2f(float x){ float y; asm("ex2.approx.f32 %0, %1;" : "=f"(y) : "f"(x)); return y; }
__device__ __forceinline__ float rcpf(float x){ float y; asm("rcp.approx.f32 %0, %1;" : "=f"(y) : "f"(x)); return y; }

// tanh(x) = 1 - 2/(1+2^(2x*log2e)) -- saturation safe, ~1e-6 abs err
__device__ __forceinline__ float tanhfast(float x){
    return 1.0f - 2.0f * rcpf(1.0f + ex2f(L2E2 * x));
}

typedef unsigned long long u64t;
__device__ __forceinline__ u64t pk(float a, float b){
    u64t r; asm("mov.b64 %0, {%1,%2};" : "=l"(r) : "f"(a), "f"(b)); return r;
}
__device__ __forceinline__ void upk(u64t v, float& a, float& b){
    asm("mov.b64 {%0,%1}, %2;" : "=f"(a), "=f"(b) : "l"(v));
}
__device__ __forceinline__ u64t ffma2(u64t a, u64t b, u64t c){
    u64t d; asm("fma.rn.f32x2 %0, %1, %2, %3;" : "=l"(d) : "l"(a), "l"(b), "l"(c)); return d;
}
__device__ __forceinline__ u64t add2(u64t a, u64t b){
    u64t d; asm("add.rn.f32x2 %0, %1, %2;" : "=l"(d) : "l"(a), "l"(b)); return d;
}
__device__ __forceinline__ void stcg_f(float* p, float v){
    asm volatile("st.global.cg.f32 [%0], %1;" :: "l"(p), "f"(v) : "memory");
}
__device__ __forceinline__ void stcg_f2(float2* p, float2 v){
    asm volatile("st.global.cg.v2.f32 [%0], {%1,%2};" :: "l"(p), "f"(v.x), "f"(v.y) : "memory");
}

// Gate rows: [0:16)=i, [16:32)=f (sigmoid, prescale -log2e);
// [32:48)=g (tanh, prescale +2log2e); [48:64)=o (sigmoid).
// After prescale: sigmoid = rcp(1+ex2(acc)); tanh = 1-2*rcp(1+ex2(acc)).
// Warp layout (batch-packed): lane L owns rows L and L+32, acc = f32x2 over (b0,b1).
// State: lane j<16 -> (b0, unit j); lane j+16 -> (b1, unit j).

// ---------------------------------------------------------------------------
// Layer 0. 4 warps/block, warp per (pair q, c, d). h broadcast via ping-pong smem.
// ---------------------------------------------------------------------------
__global__ __launch_bounds__(128, 3) void lstm_l0(
    const float* __restrict__ data,   // [B, C, T, 1]
    const float* __restrict__ Wih,    // [C, 2, 64, 1]
    const float* __restrict__ Whh,    // [C, 2, 64, 16]
    const float* __restrict__ bih,    // [C, 2, 64]
    const float* __restrict__ bhh)    // [C, 2, 64]
{
    __shared__ __align__(16) float hsm[2][4][32];
    const int warp = threadIdx.x >> 5;
    const int lane = threadIdx.x & 31;
    const int gw   = blockIdx.x * 4 + warp;   // [0, NPAIR)
    const int d    = gw & 1;
    const int rest = gw >> 1;
    const int c    = rest % C_;
    const int q    = rest / C_;               // batch pair
    const int b0   = 2*q;
    const int cd   = c*2 + d;

    const bool  lo = (lane < H_);
    const float s0 = -L2E;
    const float s1 = lo ? L2E2 : -L2E;
    const float A1 = lo ?  1.0f : 0.0f;
    const float B1 = lo ? -2.0f : 1.0f;

    const float wi0   = s0 * Wih[cd*64 + lane];
    const float wi1   = s1 * Wih[cd*64 + 32 + lane];
    const float bias0 = s0 * (bih[cd*64 + lane]      + bhh[cd*64 + lane]);
    const float bias1 = s1 * (bih[cd*64 + 32 + lane] + bhh[cd*64 + 32 + lane]);
    const u64t  bias0p = pk(bias0, bias0);
    const u64t  bias1p = pk(bias1, bias1);
    const u64t  Z = pk(0.0f, 0.0f);

    u64t w0p[16], w1p[16];
    {
        const float* r0 = Whh + (cd*64 + lane)*H_;
        const float* r1 = Whh + (cd*64 + 32 + lane)*H_;
        #pragma unroll
        for (int k = 0; k < 16; k++){
            const float a = s0*r0[k]; w0p[k] = pk(a, a);
            const float b = s1*r1[k]; w1p[k] = pk(b, b);
        }
    }

    const float* x0c = data + (size_t)(b0*C_ + c)*T_     + (d ? (T_-1) : 0);
    const float* x1c = data + (size_t)((b0+1)*C_ + c)*T_ + (d ? (T_-1) : 0);
    const int    dt  = d ? -1 : 1;
    // y store: batch b0+(lane>>4), unit lane&15
    float* ycur = g_y + ((size_t)((b0 + (lane>>4))*C_ + c)*T_ + (d ? (T_-1) : 0)) * 32
                      + d*16 + (lane & 15);
    const long   ystep = (long)dt * 32;
    const int    hidx  = (lane & 15)*2 + (lane >> 4);   // hsm slot: unit*2+par

    hsm[0][warp][hidx] = 0.0f;
    __syncwarp();

    float h = 0.0f, cst = 0.0f;
    int pb = 0;
    for (int s = 0; s < T_; s++){
        const float x0 = __ldg(x0c); x0c += dt;
        const float x1 = __ldg(x1c); x1c += dt;

        // h pairs (b0,b1) for k=0..15
        const ulonglong2* hv = (const ulonglong2*)hsm[pb][warp];
        u64t hp[16];
        #pragma unroll
        for (int m = 0; m < 8; m++){
            const ulonglong2 v = hv[m];
            hp[2*m] = v.x; hp[2*m+1] = v.y;
        }

        u64t a0A = bias0p, a0B = Z, a1A = bias1p, a1B = Z;
        #pragma unroll
        for (int j = 0; j < 8; j++){
            a0A = ffma2(w0p[j],   hp[j],   a0A);
            a0B = ffma2(w0p[j+8], hp[j+8], a0B);
            a1A = ffma2(w1p[j],   hp[j],   a1A);
            a1B = ffma2(w1p[j+8], hp[j+8], a1B);
        }
        float e0, e1, f0, f1;
        upk(add2(a0A, a0B), e0, e1);
        const float p0x = fmaf(x0, wi0, e0);
        const float p0y = fmaf(x1, wi0, e1);
        upk(add2(a1A, a1B), f0, f1);
        const float p1x = fmaf(x0, wi1, f0);
        const float p1y = fmaf(x1, wi1, f1);

        const float r0x = rcpf(1.0f + ex2f(p0x));   // sigmoid: i (lo) / f (hi), b0
        const float r0y = rcpf(1.0f + ex2f(p0y));   // b1
        const float r1x = fmaf(B1, rcpf(1.0f + ex2f(p1x)), A1);  // g (lo) / o (hi), b0
        const float r1y = fmaf(B1, rcpf(1.0f + ex2f(p1y)), A1);  // b1

        const float recv0 = __shfl_xor_sync(0xffffffffu, lo ? r0y : r0x, 16);
        const float recv1 = __shfl_xor_sync(0xffffffffu, lo ? r1y : r1x, 16);

        const float gi = lo ? r0x  : recv0;   // input gate for own (unit,batch)
        const float gf = lo ? recv0 : r0y;    // forget gate
        const float gg = lo ? r1x  : recv1;   // cell gate (tanh)
        const float go = lo ? recv1 : r1y;    // output gate

        cst = fmaf(gf, cst, gi * gg);
        h   = go * tanhfast(cst);

        hsm[pb ^ 1][warp][hidx] = h;
        __syncwarp();
        pb ^= 1;
        stcg_f(ycur, h);          // streaming store: consumed by l1_pre via L2
        ycur += ystep;
    }
}

// ---------------------------------------------------------------------------
// Layer-1 input GEMM, batch-pair blocks: pre[cd][q][t][g*2+par] =
//   prescale * (Wih1 . y[b][c][t][:] + bias),  both parities per block.
// Grid: 3072 blocks x 128 threads; warp handles 256 t's for (cd,q).
// ---------------------------------------------------------------------------
__global__ __launch_bounds__(128) void l1_pre(
    const float* __restrict__ Wih,    // [C, 2, 64, 32]
    const float* __restrict__ bih,
    const float* __restrict__ bhh)
{
    const int blk  = blockIdx.x;          // 0..3071
    const int pr   = blk >> 1;            // 0..1535 : (cd, q)
    const int th   = blk & 1;             // t-half
    const int cd   = pr / 128;
    const int q    = pr % 128;
    const int c    = cd >> 1;
    const int b0   = 2*q;
    const int warp = threadIdx.x >> 5;
    const int lane = threadIdx.x & 31;

    const bool  lo = (lane < H_);
    const float s0 = -L2E;
    const float s1 = lo ? L2E2 : -L2E;

    u64t w0[16], w1[16];   // k-packed rows lane, lane+32
    {
        const float* r0 = Wih + (size_t)(cd*64 + lane)*32;
        const float* r1 = Wih + (size_t)(cd*64 + 32 + lane)*32;
        #pragma unroll
        for (int j = 0; j < 16; j++){
            w0[j] = pk(s0*r0[2*j], s0*r0[2*j+1]);
            w1[j] = pk(s1*r1[2*j], s1*r1[2*j+1]);
        }
    }
    const float bias0 = s0 * (bih[cd*64 + lane]      + bhh[cd*64 + lane]);
    const float bias1 = s1 * (bih[cd*64 + 32 + lane] + bhh[cd*64 + 32 + lane]);

    const float* y0base = g_y + ((size_t)(b0*C_ + c)*T_)*32;
    const float* y1base = g_y + ((size_t)((b0+1)*C_ + c)*T_)*32;
    float*       pbase  = g_pre + PADF + ((size_t)(cd*128 + q)*T_)*128;

    const int t0 = th*1024 + warp*256;
    #pragma unroll 2
    for (int t = t0; t < t0 + 256; t++){
        const ulonglong2* yr0 = (const ulonglong2*)(y0base + (size_t)t*32);
        const ulonglong2* yr1 = (const ulonglong2*)(y1base + (size_t)t*32);

        u64t a00 = pk(bias0, 0.f), a01 = pk(0.f, 0.f);   // row0, b0 : k-split chains
        u64t b00 = pk(bias0, 0.f), b01 = pk(0.f, 0.f);   // row0, b1
        u64t a10 = pk(bias1, 0.f), a11 = pk(0.f, 0.f);   // row1, b0
        u64t b10 = pk(bias1, 0.f), b11 = pk(0.f, 0.f);   // row1, b1
        #pragma unroll
        for (int m = 0; m < 8; m++){
            const ulonglong2 v0 = __ldg(yr0 + m);
            const ulonglong2 v1 = __ldg(yr1 + m);
            a00 = ffma2(w0[2*m],   v0.x, a00);
            a01 = ffma2(w0[2*m+1], v0.y, a01);
            b00 = ffma2(w0[2*m],   v1.x, b00);
            b01 = ffma2(w0[2*m+1], v1.y, b01);
            a10 = ffma2(w1[2*m],   v0.x, a10);
            a11 = ffma2(w1[2*m+1], v0.y, a11);
            b10 = ffma2(w1[2*m],   v1.x, b10);
            b11 = ffma2(w1[2*m+1], v1.y, b11);
        }
        float e0,e1,f0,f1;
        upk(add2(a00,a01), e0, e1); const float p0b0 = e0 + e1;
        upk(add2(b00,b01), f0, f1); const float p0b1 = f0 + f1;
        upk(add2(a10,a11), e0, e1); const float p1b0 = e0 + e1;
        upk(add2(b10,b11), f0, f1); const float p1b1 = f0 + f1;

        float2* pr2 = (float2*)(pbase + (size_t)t*128);
        stcg_f2(pr2 + lane,      make_float2(p0b0, p0b1));   // gate lane,    (par0,par1)
        stcg_f2(pr2 + lane + 32, make_float2(p1b0, p1b1));   // gate lane+32
    }
}

// ---------------------------------------------------------------------------
// Layer 1 recurrence, batch-packed. Per step: 2 LDG.64 (pre pairs, dist-4 ring),
// h-matvec 32 ffma2, activations, exchange. Single wave at 3 blocks/SM.
// ---------------------------------------------------------------------------
__global__ __launch_bounds__(128, 3) void lstm_l1(
    const float* __restrict__ Whh,    // [C, 2, 64, 16]
    float* __restrict__ out)          // [B, C*32]
{
    __shared__ __align__(16) float hsm[2][4][32];
    const int warp = threadIdx.x >> 5;
    const int lane = threadIdx.x & 31;
    const int gw   = blockIdx.x * 4 + warp;
    const int d    = gw & 1;
    const int rest = gw >> 1;
    const int c    = rest % C_;
    const int q    = rest / C_;
    const int b0   = 2*q;
    const int cd   = c*2 + d;

    const bool  lo = (lane < H_);
    const float A1 = lo ?  1.0f : 0.0f;
    const float B1 = lo ? -2.0f : 1.0f;
    const float s0 = -L2E;
    const float s1 = lo ? L2E2 : -L2E;
    const u64t  Z  = pk(0.0f, 0.0f);

    u64t w0p[16], w1p[16];
    {
        const float* r0 = Whh + (cd*64 + lane)*H_;
        const float* r1 = Whh + (cd*64 + 32 + lane)*H_;
        #pragma unroll
        for (int k = 0; k < 16; k++){
            const float a = s0*r0[k]; w0p[k] = pk(a, a);
            const float b = s1*r1[k]; w1p[k] = pk(b, b);
        }
    }

    // pre pointers (float2 units): row stride 64 float2
    const float2* pq = (const float2*)(g_pre + PADF)
        + (((size_t)(cd*128 + q))*T_ + (d ? (T_-1) : 0))*64 + lane;
    const long pstep = d ? -64l : 64l;

    float2 rr0[4], rr1[4];
    #pragma unroll
    for (int i = 0; i < 4; i++){
        rr0[i] = __ldg(pq);        // gate row `lane`, pair (b0,b1)
        rr1[i] = __ldg(pq + 32);   // gate row `lane+32`
        pq += pstep;
    }

    const int hidx = (lane & 15)*2 + (lane >> 4);
    hsm[0][warp][hidx] = 0.0f;
    __syncwarp();

    float h = 0.0f, cst = 0.0f;
    int pb = 0;
    for (int s = 0; s < T_; s += 4){
        #pragma unroll
        for (int u = 0; u < 4; u++){
            const float2 nv0 = __ldg(pq);
            const float2 nv1 = __ldg(pq + 32);
            pq += pstep;

            const ulonglong2* hv = (const ulonglong2*)hsm[pb][warp];
            u64t hp[16];
            #pragma unroll
            for (int m = 0; m < 8; m++){
                const ulonglong2 v = hv[m];
                hp[2*m] = v.x; hp[2*m+1] = v.y;
            }

            u64t a0A = pk(rr0[u].x, rr0[u].y), a0B = Z;
            u64t a1A = pk(rr1[u].x, rr1[u].y), a1B = Z;
            #pragma unroll
            for (int j = 0; j < 8; j++){
                a0A = ffma2(w0p[j],   hp[j],   a0A);
                a0B = ffma2(w0p[j+8], hp[j+8], a0B);
                a1A = ffma2(w1p[j],   hp[j],   a1A);
                a1B = ffma2(w1p[j+8], hp[j+8], a1B);
            }
            float p0x, p0y, p1x, p1y;
            {
                float e0,e1; upk(add2(a0A,a0B), e0, e1); p0x = e0; p0y = e1;
                float f0,f1; upk(add2(a1A,a1B), f0, f1); p1x = f0; p1y = f1;
            }

            const float r0x = rcpf(1.0f + ex2f(p0x));
            const float r0y = rcpf(1.0f + ex2f(p0y));
            const float r1x = fmaf(B1, rcpf(1.0f + ex2f(p1x)), A1);
            const float r1y = fmaf(B1, rcpf(1.0f + ex2f(p1y)), A1);

            const float recv0 = __shfl_xor_sync(0xffffffffu, lo ? r0y : r0x, 16);
            const float recv1 = __shfl_xor_sync(0xffffffffu, lo ? r1y : r1x, 16);

            const float gi = lo ? r0x  : recv0;
            const float gf = lo ? recv0 : r0y;
            const float gg = lo ? r1x  : recv1;
            const float go = lo ? recv1 : r1y;

            cst = fmaf(gf, cst, gi * gg);
            h   = go * tanhfast(cst);

            hsm[pb ^ 1][warp][hidx] = h;
            __syncwarp();
            pb ^= 1;
            rr0[u] = nv0; rr1[u] = nv1;
        }
    }

    // lane j<16 -> (b0, unit j); lane j+16 -> (b1, unit j)
    out[(b0 + (lane>>4))*(C_*32) + c*32 + d*16 + (lane & 15)] = h;
}

extern "C" void kernel_launch(void* const* d_in, const int* in_sizes, int n_in,
                              void* d_out, int out_size)
{
    const float* data = (const float*)d_in[0];
    const float* Wih0 = (const float*)d_in[1];
    const float* Whh0 = (const float*)d_in[2];
    const float* bih0 = (const float*)d_in[3];
    const float* bhh0 = (const float*)d_in[4];
    const float* Wih1 = (const float*)d_in[5];
    const float* Whh1 = (const float*)d_in[6];
    const float* bih1 = (const float*)d_in[7];
    const float* bhh1 = (const float*)d_in[8];

    lstm_l0<<<NPAIR/4, 128>>>(data, Wih0, Whh0, bih0, bhh0);
    l1_pre<<<NPAIR*2, 128>>>(Wih1, bih1, bhh1);
    lstm_l1<<<NPAIR/4, 128>>>(Whh1, (float*)d_out);
}